// round 14
// baseline (speedup 1.0000x reference)
#include <cuda_runtime.h>
#include <cuda_fp16.h>
#include <math.h>

#define N_NODES 100000
#define N_EDGES 3200000
#define IN_DIM  500
#define HID     64
#define HID2    (HID / 2)
#define OUT_DIM 40
#define K_STEPS 10
#define SCAN_TILE 1024
#define NUM_TILES ((N_NODES + SCAN_TILE - 1) / SCAN_TILE)   // 98
#define NB_E ((N_EDGES + 255) / 256)                        // 12500
#define NB_N ((N_NODES + 255) / 256)                        // 391
#define GEMM_BM 128
#define NB_G ((N_NODES + GEMM_BM - 1) / GEMM_BM)            // 782
#define XS_STRIDE 132   // words; 132*4B=528B rows keep 16B alignment for LDS.128

// ---------------- device scratch (static: no allocations allowed) -------------
__device__ int   g_counts[N_NODES];
__device__ float g_dinv[N_NODES];
__device__ int   g_ptr[N_NODES];          // tile-local exclusive prefix
__device__ int   g_ptrF[N_NODES + 1];     // final global CSR row pointers
__device__ int   g_cursor[N_NODES];       // tile-local running cursor for scatter
__device__ int   g_tilesum[NUM_TILES];
__device__ __align__(16)  int2    g_edges[N_EDGES];              // (src, norm), dst-sorted
__device__ __align__(128) float   g_h0[(size_t)N_NODES * HID];   // fp32 anchor
__device__ __align__(128) float   g_hf32[(size_t)N_NODES * HID]; // fp32 final
__device__ __align__(128) __half2 g_h16A[(size_t)N_NODES * HID2];
__device__ __align__(128) __half2 g_h16B[(size_t)N_NODES * HID2];

__device__ __forceinline__ __half2* h16buf(int s) { return s ? g_h16B : g_h16A; }

// ---------------- f32x2 packed-FMA helpers -----------------------------------
#define FMA2(acc, a, b) \
    asm("fma.rn.f32x2 %0, %1, %2, %0;" : "+l"(acc) : "l"(a), "l"(b))
#define PACK_DUP(dst, x) \
    asm("mov.b64 %0, {%1, %1};" : "=l"(dst) : "f"(x))
#define UNPACK2(lo, hi, v) \
    asm("mov.b64 {%0, %1}, %2;" : "=f"(lo), "=f"(hi) : "l"(v))

// ---------------- launch 1: degree count --------------------------------------
__global__ void k_count(const int* __restrict__ col) {
    int e = blockIdx.x * blockDim.x + threadIdx.x;
    if (e < N_EDGES) atomicAdd(&g_counts[col[e]], 1);
}

// ---------------- launch 2: tile scan + dinv + cursor init + count re-zero ----
__global__ void __launch_bounds__(SCAN_TILE) k_scanA() {
    __shared__ int s[SCAN_TILE];
    const int t = threadIdx.x;
    const int gid = blockIdx.x * SCAN_TILE + t;
    int v = 0;
    if (gid < N_NODES) {
        v = g_counts[gid];
        g_counts[gid] = 0;                         // ready for next replay
        g_dinv[gid] = rsqrtf((float)(v + 1));      // +1 self loop
    }
    s[t] = v;
    __syncthreads();
#pragma unroll
    for (int off = 1; off < SCAN_TILE; off <<= 1) {
        int u = (t >= off) ? s[t - off] : 0;
        __syncthreads();
        s[t] += u;
        __syncthreads();
    }
    if (gid < N_NODES) {
        int p = s[t] - v;                          // tile-local exclusive
        g_ptr[gid] = p;
        g_cursor[gid] = p;
    }
    if (t == SCAN_TILE - 1) g_tilesum[blockIdx.x] = s[t];
}

// ---------------- launch 3: scatter (+ inline tile-offset scan + final ptr) ---
__global__ void __launch_bounds__(256) k_scatter(const int* __restrict__ ei) {
    __shared__ int s[128];
    __shared__ int s_off[128];
    const int t = threadIdx.x;

    if (t < 128) s[t] = (t < NUM_TILES) ? g_tilesum[t] : 0;
    __syncthreads();
#pragma unroll
    for (int off = 1; off < 128; off <<= 1) {
        int u = 0;
        if (t < 128 && t >= off) u = s[t - off];
        __syncthreads();
        if (t < 128) s[t] += u;
        __syncthreads();
    }
    if (t < 128) s_off[t] = s[t] - ((t < NUM_TILES) ? g_tilesum[t] : 0);
    __syncthreads();

    int e = blockIdx.x * 256 + t;

    if (e <= N_NODES)
        g_ptrF[e] = (e == N_NODES) ? N_EDGES : (g_ptr[e] + s_off[e >> 10]);

    if (e >= N_EDGES) return;
    int r = ei[e];               // src
    int c = ei[N_EDGES + e];     // dst
    float nrm = g_dinv[r] * g_dinv[c];
    int pos = atomicAdd(&g_cursor[c], 1) + s_off[c >> 10];
    g_edges[pos] = make_int2(r, __float_as_int(nrm));
}

// ---------------- launch 4: lin1 GEMM — 2D register tiling, k-major x tile ----
__global__ void __launch_bounds__(128) k_gemm1(const float* __restrict__ x,
                                               const float* __restrict__ W1,
                                               const float* __restrict__ b1) {
    __shared__ __align__(16) float Ws[32 * 64];          // 8 KB
    __shared__ __align__(16) float xsc[32 * XS_STRIDE];  // 16.9 KB, k-major

    const int tid = threadIdx.x;
    const int tr = tid >> 3;         // 0..15 -> rows tr*8..tr*8+7
    const int tc = tid & 7;          // cols tc*8..tc*8+7
    const int rowbase = blockIdx.x * GEMM_BM;

    unsigned long long acc2[8][4];
    {
        unsigned long long bias2[4];
#pragma unroll
        for (int j2 = 0; j2 < 4; j2++)
            bias2[j2] = *(const unsigned long long*)&b1[tc * 8 + j2 * 2];
#pragma unroll
        for (int i = 0; i < 8; i++)
#pragma unroll
            for (int j2 = 0; j2 < 4; j2++)
                acc2[i][j2] = bias2[j2];
    }

    for (int kc = 0; kc < IN_DIM; kc += 32) {
        __syncthreads();
        // stage W chunk: 32 x 64 floats = 512 float4
#pragma unroll
        for (int it = 0; it < 4; it++) {
            int idx = it * 128 + tid;
            int kk = idx >> 4, j4 = idx & 15;
            float4 v = make_float4(0.f, 0.f, 0.f, 0.f);
            if (kc + kk < IN_DIM)
                v = *(const float4*)&W1[(size_t)(kc + kk) * HID + j4 * 4];
            *(float4*)&Ws[kk * 64 + j4 * 4] = v;
        }
        // stage x chunk k-major: coalesced float4 LDG, scattered scalar STS
#pragma unroll
        for (int it = 0; it < 8; it++) {
            int idx = it * 128 + tid;
            int r = idx >> 3, c4 = idx & 7;
            int grow = rowbase + r;
            if (grow >= N_NODES) grow = N_NODES - 1;
            int col = kc + c4 * 4;
            float4 v = make_float4(0.f, 0.f, 0.f, 0.f);
            if (col < IN_DIM)
                v = *(const float4*)&x[(size_t)grow * IN_DIM + col];
            int kb = c4 * 4;
            xsc[(kb + 0) * XS_STRIDE + r] = v.x;
            xsc[(kb + 1) * XS_STRIDE + r] = v.y;
            xsc[(kb + 2) * XS_STRIDE + r] = v.z;
            xsc[(kb + 3) * XS_STRIDE + r] = v.w;
        }
        __syncthreads();

#pragma unroll 8
        for (int kk = 0; kk < 32; kk++) {
            ulonglong2 w0 = *(const ulonglong2*)&Ws[kk * 64 + tc * 8];
            ulonglong2 w1 = *(const ulonglong2*)&Ws[kk * 64 + tc * 8 + 4];
            float4 xa = *(const float4*)&xsc[kk * XS_STRIDE + tr * 8];
            float4 xb = *(const float4*)&xsc[kk * XS_STRIDE + tr * 8 + 4];
            unsigned long long xd;
            PACK_DUP(xd, xa.x);
            FMA2(acc2[0][0], xd, w0.x); FMA2(acc2[0][1], xd, w0.y);
            FMA2(acc2[0][2], xd, w1.x); FMA2(acc2[0][3], xd, w1.y);
            PACK_DUP(xd, xa.y);
            FMA2(acc2[1][0], xd, w0.x); FMA2(acc2[1][1], xd, w0.y);
            FMA2(acc2[1][2], xd, w1.x); FMA2(acc2[1][3], xd, w1.y);
            PACK_DUP(xd, xa.z);
            FMA2(acc2[2][0], xd, w0.x); FMA2(acc2[2][1], xd, w0.y);
            FMA2(acc2[2][2], xd, w1.x); FMA2(acc2[2][3], xd, w1.y);
            PACK_DUP(xd, xa.w);
            FMA2(acc2[3][0], xd, w0.x); FMA2(acc2[3][1], xd, w0.y);
            FMA2(acc2[3][2], xd, w1.x); FMA2(acc2[3][3], xd, w1.y);
            PACK_DUP(xd, xb.x);
            FMA2(acc2[4][0], xd, w0.x); FMA2(acc2[4][1], xd, w0.y);
            FMA2(acc2[4][2], xd, w1.x); FMA2(acc2[4][3], xd, w1.y);
            PACK_DUP(xd, xb.y);
            FMA2(acc2[5][0], xd, w0.x); FMA2(acc2[5][1], xd, w0.y);
            FMA2(acc2[5][2], xd, w1.x); FMA2(acc2[5][3], xd, w1.y);
            PACK_DUP(xd, xb.z);
            FMA2(acc2[6][0], xd, w0.x); FMA2(acc2[6][1], xd, w0.y);
            FMA2(acc2[6][2], xd, w1.x); FMA2(acc2[6][3], xd, w1.y);
            PACK_DUP(xd, xb.w);
            FMA2(acc2[7][0], xd, w0.x); FMA2(acc2[7][1], xd, w0.y);
            FMA2(acc2[7][2], xd, w1.x); FMA2(acc2[7][3], xd, w1.y);
        }
    }

#pragma unroll
    for (int i = 0; i < 8; i++) {
        int row = rowbase + tr * 8 + i;
        if (row < N_NODES) {
            float f0, f1, f2, f3, f4, f5, f6, f7;
            UNPACK2(f0, f1, acc2[i][0]);
            UNPACK2(f2, f3, acc2[i][1]);
            UNPACK2(f4, f5, acc2[i][2]);
            UNPACK2(f6, f7, acc2[i][3]);
            float* h0p = g_h0 + (size_t)row * HID + tc * 8;
            *(float4*)&h0p[0] = make_float4(f0, f1, f2, f3);
            *(float4*)&h0p[4] = make_float4(f4, f5, f6, f7);
            __half2 p0 = __floats2half2_rn(f0, f1);
            __half2 p1 = __floats2half2_rn(f2, f3);
            __half2 p2 = __floats2half2_rn(f4, f5);
            __half2 p3 = __floats2half2_rn(f6, f7);
            uint4 ov;
            ov.x = *(unsigned*)&p0;
            ov.y = *(unsigned*)&p1;
            ov.z = *(unsigned*)&p2;
            ov.w = *(unsigned*)&p3;
            *(uint4*)(g_h16A + (size_t)row * HID2 + tc * 4) = ov;
        }
    }
}

// ---------------- launches 5..14: APPNP propagation ---------------------------
// Warp-per-node, 4 edges per iteration across quarter-warps. Full batches use
// explicit groups of 4 batched LDG.128 (vv[4] in flight) — no occupancy cap,
// ~60 regs, no spills (lesson from R12).
#define ACC8(n, v)                                              \
    do {                                                        \
        float2 _f0 = __half22float2(*(__half2*)&(v).x);         \
        float2 _f1 = __half22float2(*(__half2*)&(v).y);         \
        float2 _f2 = __half22float2(*(__half2*)&(v).z);         \
        float2 _f3 = __half22float2(*(__half2*)&(v).w);         \
        a0 = fmaf((n), _f0.x, a0);  a1 = fmaf((n), _f0.y, a1);  \
        a2 = fmaf((n), _f1.x, a2);  a3 = fmaf((n), _f1.y, a3);  \
        a4 = fmaf((n), _f2.x, a4);  a5 = fmaf((n), _f2.y, a5);  \
        a6 = fmaf((n), _f3.x, a6);  a7 = fmaf((n), _f3.y, a7);  \
    } while (0)

__global__ void __launch_bounds__(256) k_prop(int sin_sel, int sout_sel, int final_step) {
    const uint4* __restrict__ xin4 = (const uint4*)h16buf(sin_sel);   // row = 8 uint4
    uint4* __restrict__ xout4 = (uint4*)h16buf(sout_sel);

    const int node = (blockIdx.x * blockDim.x + threadIdx.x) >> 5;
    const int lane = threadIdx.x & 31;
    if (node >= N_NODES) return;

    const int beg = g_ptrF[node];
    const int end = g_ptrF[node + 1];
    const int deg = end - beg;
    const int nfull = deg & ~31;
    const int q   = lane >> 3;       // quarter id 0..3
    const int sub = lane & 7;        // uint4 index within 128B row

    float a0 = 0.f, a1 = 0.f, a2 = 0.f, a3 = 0.f;
    float a4 = 0.f, a5 = 0.f, a6 = 0.f, a7 = 0.f;

    int base = beg;
    for (; base < beg + nfull; base += 32) {
        int2 ed = g_edges[base + lane];
#pragma unroll
        for (int jj = 0; jj < 8; jj += 4) {
            // phase 1: all shuffles for this group of 4
            int   s0 = __shfl_sync(0xffffffffu, ed.x, jj + 0 + q * 8);
            int   s1 = __shfl_sync(0xffffffffu, ed.x, jj + 1 + q * 8);
            int   s2 = __shfl_sync(0xffffffffu, ed.x, jj + 2 + q * 8);
            int   s3 = __shfl_sync(0xffffffffu, ed.x, jj + 3 + q * 8);
            float n0 = __int_as_float(__shfl_sync(0xffffffffu, ed.y, jj + 0 + q * 8));
            float n1 = __int_as_float(__shfl_sync(0xffffffffu, ed.y, jj + 1 + q * 8));
            float n2 = __int_as_float(__shfl_sync(0xffffffffu, ed.y, jj + 2 + q * 8));
            float n3 = __int_as_float(__shfl_sync(0xffffffffu, ed.y, jj + 3 + q * 8));
            // phase 2: 4 independent LDG.128 in flight
            uint4 v0 = xin4[s0 * 8 + sub];
            uint4 v1 = xin4[s1 * 8 + sub];
            uint4 v2 = xin4[s2 * 8 + sub];
            uint4 v3 = xin4[s3 * 8 + sub];
            // phase 3: consume
            ACC8(n0, v0);
            ACC8(n1, v1);
            ACC8(n2, v2);
            ACC8(n3, v3);
        }
    }

    const int rem = deg - nfull;
    if (rem) {
        int idx = base + lane;
        int2 ed = (idx < end) ? g_edges[idx] : make_int2(0, 0);
        const int half = (rem + 3) >> 2;            // <= 8
        for (int j = 0; j < half; j++) {
            int   sl = j + q * half;                // <= 31
            int   s  = __shfl_sync(0xffffffffu, ed.x, sl);
            float n  = __int_as_float(__shfl_sync(0xffffffffu, ed.y, sl));
            uint4 v  = xin4[s * 8 + sub];
            ACC8(n, v);
        }
    }

    a0 += __shfl_down_sync(0xffffffffu, a0, 16);
    a1 += __shfl_down_sync(0xffffffffu, a1, 16);
    a2 += __shfl_down_sync(0xffffffffu, a2, 16);
    a3 += __shfl_down_sync(0xffffffffu, a3, 16);
    a4 += __shfl_down_sync(0xffffffffu, a4, 16);
    a5 += __shfl_down_sync(0xffffffffu, a5, 16);
    a6 += __shfl_down_sync(0xffffffffu, a6, 16);
    a7 += __shfl_down_sync(0xffffffffu, a7, 16);
    a0 += __shfl_down_sync(0xffffffffu, a0, 8);
    a1 += __shfl_down_sync(0xffffffffu, a1, 8);
    a2 += __shfl_down_sync(0xffffffffu, a2, 8);
    a3 += __shfl_down_sync(0xffffffffu, a3, 8);
    a4 += __shfl_down_sync(0xffffffffu, a4, 8);
    a5 += __shfl_down_sync(0xffffffffu, a5, 8);
    a6 += __shfl_down_sync(0xffffffffu, a6, 8);
    a7 += __shfl_down_sync(0xffffffffu, a7, 8);

    if (lane < 8) {
        float dv = g_dinv[node];
        float sn = dv * dv;
        uint4 sv = xin4[node * 8 + sub];
        {
            float2 f0 = __half22float2(*(__half2*)&sv.x);
            float2 f1 = __half22float2(*(__half2*)&sv.y);
            float2 f2 = __half22float2(*(__half2*)&sv.z);
            float2 f3 = __half22float2(*(__half2*)&sv.w);
            a0 = fmaf(sn, f0.x, a0);  a1 = fmaf(sn, f0.y, a1);
            a2 = fmaf(sn, f1.x, a2);  a3 = fmaf(sn, f1.y, a3);
            a4 = fmaf(sn, f2.x, a4);  a5 = fmaf(sn, f2.y, a5);
            a6 = fmaf(sn, f3.x, a6);  a7 = fmaf(sn, f3.y, a7);
        }

        const float4* h0p = (const float4*)(g_h0 + (size_t)node * HID) + sub * 2;
        float4 h0a = h0p[0];
        float4 h0b = h0p[1];
        float o0 = 0.9f * a0 + 0.1f * h0a.x;
        float o1 = 0.9f * a1 + 0.1f * h0a.y;
        float o2 = 0.9f * a2 + 0.1f * h0a.z;
        float o3 = 0.9f * a3 + 0.1f * h0a.w;
        float o4 = 0.9f * a4 + 0.1f * h0b.x;
        float o5 = 0.9f * a5 + 0.1f * h0b.y;
        float o6 = 0.9f * a6 + 0.1f * h0b.z;
        float o7 = 0.9f * a7 + 0.1f * h0b.w;

        __half2 p0 = __floats2half2_rn(o0, o1);
        __half2 p1 = __floats2half2_rn(o2, o3);
        __half2 p2 = __floats2half2_rn(o4, o5);
        __half2 p3 = __floats2half2_rn(o6, o7);
        uint4 ov;
        ov.x = *(unsigned*)&p0;
        ov.y = *(unsigned*)&p1;
        ov.z = *(unsigned*)&p2;
        ov.w = *(unsigned*)&p3;
        xout4[node * 8 + sub] = ov;

        if (final_step) {
            float4* fo = (float4*)(g_hf32 + (size_t)node * HID) + sub * 2;
            fo[0] = make_float4(o0, o1, o2, o3);
            fo[1] = make_float4(o4, o5, o6, o7);
        }
    }
}

// ---------------- BN + lin2 + log_softmax (fused epilogue) --------------------
__global__ void __launch_bounds__(128) k_epilogue(const float* __restrict__ gamma,
                                                  const float* __restrict__ beta,
                                                  const float* __restrict__ mean,
                                                  const float* __restrict__ var,
                                                  const float* __restrict__ W2,
                                                  const float* __restrict__ b2,
                                                  float* __restrict__ out) {
    __shared__ float sc[HID], sh[HID];
    __shared__ float W2s[HID * OUT_DIM];
    __shared__ float b2s[OUT_DIM];

    const int tid = threadIdx.x;
    if (tid < HID) {
        float s = gamma[tid] * rsqrtf(var[tid] + 1e-5f);
        sc[tid] = s;
        sh[tid] = beta[tid] - mean[tid] * s;
    }
    if (tid < OUT_DIM) b2s[tid] = b2[tid];
    for (int i = tid; i < HID * OUT_DIM; i += 128) W2s[i] = W2[i];
    __syncthreads();

    int node = blockIdx.x * 128 + tid;
    if (node >= N_NODES) return;

    float acc[OUT_DIM];
#pragma unroll
    for (int j = 0; j < OUT_DIM; j++) acc[j] = b2s[j];

    const float* hp = g_hf32 + (size_t)node * HID;
    for (int k = 0; k < HID; k++) {
        float t = fmaf(hp[k], sc[k], sh[k]);
#pragma unroll
        for (int j = 0; j < OUT_DIM; j++)
            acc[j] = fmaf(t, W2s[k * OUT_DIM + j], acc[j]);
    }

    float m = acc[0];
#pragma unroll
    for (int j = 1; j < OUT_DIM; j++) m = fmaxf(m, acc[j]);
    float s = 0.f;
#pragma unroll
    for (int j = 0; j < OUT_DIM; j++) s += expf(acc[j] - m);
    float lse = m + logf(s);

    float* op = out + (size_t)node * OUT_DIM;
    float* ep = out + (size_t)N_NODES * OUT_DIM + (size_t)node * OUT_DIM;
#pragma unroll
    for (int j4 = 0; j4 < OUT_DIM / 4; j4++) {
        float4 e = make_float4(acc[4*j4], acc[4*j4+1], acc[4*j4+2], acc[4*j4+3]);
        float4 o = make_float4(e.x - lse, e.y - lse, e.z - lse, e.w - lse);
        *(float4*)&op[4 * j4] = o;
        *(float4*)&ep[4 * j4] = e;
    }
}

// ---------------- host launcher -----------------------------------------------
extern "C" void kernel_launch(void* const* d_in, const int* in_sizes, int n_in,
                              void* d_out, int out_size) {
    const float* x     = (const float*)d_in[0];
    const int*   ei    = (const int*)d_in[1];     // int64 inputs delivered as int32
    const float* W1    = (const float*)d_in[2];
    const float* b1    = (const float*)d_in[3];
    const float* gamma = (const float*)d_in[4];
    const float* beta  = (const float*)d_in[5];
    const float* mean  = (const float*)d_in[6];
    const float* var   = (const float*)d_in[7];
    const float* W2    = (const float*)d_in[8];
    const float* b2    = (const float*)d_in[9];
    float*       out   = (float*)d_out;

    k_count<<<NB_E, 256>>>(ei + N_EDGES);
    k_scanA<<<NUM_TILES, SCAN_TILE>>>();
    k_scatter<<<NB_E, 256>>>(ei);
    k_gemm1<<<NB_G, 128>>>(x, W1, b1);

    const int prop_blocks = (N_NODES * 32 + 255) / 256;
    for (int s = 0; s < K_STEPS; s++)
        k_prop<<<prop_blocks, 256>>>(s & 1, (s & 1) ^ 1, s == K_STEPS - 1);

    k_epilogue<<<(N_NODES + 127) / 128, 128>>>(gamma, beta, mean, var, W2, b2, out);
}

// round 15
// speedup vs baseline: 1.1380x; 1.1380x over previous
#include <cuda_runtime.h>
#include <cuda_fp16.h>
#include <math.h>

#define N_NODES 100000
#define N_EDGES 3200000
#define IN_DIM  500
#define HID     64
#define HID2    (HID / 2)
#define OUT_DIM 40
#define K_STEPS 10
#define SCAN_TILE 1024
#define NUM_TILES ((N_NODES + SCAN_TILE - 1) / SCAN_TILE)   // 98
#define NB_E ((N_EDGES + 255) / 256)                        // 12500
#define NB_N ((N_NODES + 255) / 256)                        // 391
#define GEMM_BM 128
#define NB_G ((N_NODES + GEMM_BM - 1) / GEMM_BM)            // 782
#define XS_STRIDE 132   // words; 132*4B=528B rows keep 16B alignment for LDS.128

// ---------------- device scratch (static: no allocations allowed) -------------
__device__ int   g_counts[N_NODES];
__device__ float g_dinv[N_NODES];
__device__ int   g_ptr[N_NODES];          // tile-local exclusive prefix
__device__ int   g_ptrF[N_NODES + 1];     // final global CSR row pointers
__device__ int   g_cursor[N_NODES];       // tile-local running cursor for scatter
__device__ int   g_tilesum[NUM_TILES];
__device__ __align__(16)  int2    g_edges[N_EDGES];              // (src, norm), dst-sorted
__device__ __align__(128) float   g_h0[(size_t)N_NODES * HID];   // fp32 anchor
__device__ __align__(128) float   g_hf32[(size_t)N_NODES * HID]; // fp32 final
__device__ __align__(128) __half2 g_h16A[(size_t)N_NODES * HID2];
__device__ __align__(128) __half2 g_h16B[(size_t)N_NODES * HID2];

__device__ __forceinline__ __half2* h16buf(int s) { return s ? g_h16B : g_h16A; }

// ---------------- f32x2 packed-FMA helpers -----------------------------------
#define FMA2(acc, a, b) \
    asm("fma.rn.f32x2 %0, %1, %2, %0;" : "+l"(acc) : "l"(a), "l"(b))
#define PACK_DUP(dst, x) \
    asm("mov.b64 %0, {%1, %1};" : "=l"(dst) : "f"(x))
#define UNPACK2(lo, hi, v) \
    asm("mov.b64 {%0, %1}, %2;" : "=f"(lo), "=f"(hi) : "l"(v))

// ---------------- degree count -------------------------------------------------
__global__ void k_count(const int* __restrict__ col) {
    int e = blockIdx.x * blockDim.x + threadIdx.x;
    if (e < N_EDGES) atomicAdd(&g_counts[col[e]], 1);
}

// ---------------- tile scan + dinv + cursor init + count re-zero ---------------
__global__ void __launch_bounds__(SCAN_TILE) k_scanA() {
    __shared__ int s[SCAN_TILE];
    const int t = threadIdx.x;
    const int gid = blockIdx.x * SCAN_TILE + t;
    int v = 0;
    if (gid < N_NODES) {
        v = g_counts[gid];
        g_counts[gid] = 0;                         // ready for next replay
        g_dinv[gid] = rsqrtf((float)(v + 1));      // +1 self loop
    }
    s[t] = v;
    __syncthreads();
#pragma unroll
    for (int off = 1; off < SCAN_TILE; off <<= 1) {
        int u = (t >= off) ? s[t - off] : 0;
        __syncthreads();
        s[t] += u;
        __syncthreads();
    }
    if (gid < N_NODES) {
        int p = s[t] - v;                          // tile-local exclusive
        g_ptr[gid] = p;
        g_cursor[gid] = p;
    }
    if (t == SCAN_TILE - 1) g_tilesum[blockIdx.x] = s[t];
}

// ---------------- scatter (+ inline tile-offset scan + final ptr) --------------
__global__ void __launch_bounds__(256) k_scatter(const int* __restrict__ ei) {
    __shared__ int s[128];
    __shared__ int s_off[128];
    const int t = threadIdx.x;

    if (t < 128) s[t] = (t < NUM_TILES) ? g_tilesum[t] : 0;
    __syncthreads();
#pragma unroll
    for (int off = 1; off < 128; off <<= 1) {
        int u = 0;
        if (t < 128 && t >= off) u = s[t - off];
        __syncthreads();
        if (t < 128) s[t] += u;
        __syncthreads();
    }
    if (t < 128) s_off[t] = s[t] - ((t < NUM_TILES) ? g_tilesum[t] : 0);
    __syncthreads();

    int e = blockIdx.x * 256 + t;

    if (e <= N_NODES)
        g_ptrF[e] = (e == N_NODES) ? N_EDGES : (g_ptr[e] + s_off[e >> 10]);

    if (e >= N_EDGES) return;
    int r = ei[e];               // src
    int c = ei[N_EDGES + e];     // dst
    float nrm = g_dinv[r] * g_dinv[c];
    int pos = atomicAdd(&g_cursor[c], 1) + s_off[c >> 10];
    g_edges[pos] = make_int2(r, __float_as_int(nrm));
}

// ---------------- lin1 GEMM — 2D register tiling, k-major x tile ---------------
__global__ void __launch_bounds__(128) k_gemm1(const float* __restrict__ x,
                                               const float* __restrict__ W1,
                                               const float* __restrict__ b1) {
    __shared__ __align__(16) float Ws[32 * 64];          // 8 KB
    __shared__ __align__(16) float xsc[32 * XS_STRIDE];  // 16.9 KB, k-major

    const int tid = threadIdx.x;
    const int tr = tid >> 3;         // 0..15 -> rows tr*8..tr*8+7
    const int tc = tid & 7;          // cols tc*8..tc*8+7
    const int rowbase = blockIdx.x * GEMM_BM;

    unsigned long long acc2[8][4];
    {
        unsigned long long bias2[4];
#pragma unroll
        for (int j2 = 0; j2 < 4; j2++)
            bias2[j2] = *(const unsigned long long*)&b1[tc * 8 + j2 * 2];
#pragma unroll
        for (int i = 0; i < 8; i++)
#pragma unroll
            for (int j2 = 0; j2 < 4; j2++)
                acc2[i][j2] = bias2[j2];
    }

    for (int kc = 0; kc < IN_DIM; kc += 32) {
        __syncthreads();
        // stage W chunk: 32 x 64 floats = 512 float4
#pragma unroll
        for (int it = 0; it < 4; it++) {
            int idx = it * 128 + tid;
            int kk = idx >> 4, j4 = idx & 15;
            float4 v = make_float4(0.f, 0.f, 0.f, 0.f);
            if (kc + kk < IN_DIM)
                v = *(const float4*)&W1[(size_t)(kc + kk) * HID + j4 * 4];
            *(float4*)&Ws[kk * 64 + j4 * 4] = v;
        }
        // stage x chunk k-major: coalesced float4 LDG, scattered scalar STS
#pragma unroll
        for (int it = 0; it < 8; it++) {
            int idx = it * 128 + tid;
            int r = idx >> 3, c4 = idx & 7;
            int grow = rowbase + r;
            if (grow >= N_NODES) grow = N_NODES - 1;
            int col = kc + c4 * 4;
            float4 v = make_float4(0.f, 0.f, 0.f, 0.f);
            if (col < IN_DIM)
                v = *(const float4*)&x[(size_t)grow * IN_DIM + col];
            int kb = c4 * 4;
            xsc[(kb + 0) * XS_STRIDE + r] = v.x;
            xsc[(kb + 1) * XS_STRIDE + r] = v.y;
            xsc[(kb + 2) * XS_STRIDE + r] = v.z;
            xsc[(kb + 3) * XS_STRIDE + r] = v.w;
        }
        __syncthreads();

#pragma unroll 8
        for (int kk = 0; kk < 32; kk++) {
            ulonglong2 w0 = *(const ulonglong2*)&Ws[kk * 64 + tc * 8];
            ulonglong2 w1 = *(const ulonglong2*)&Ws[kk * 64 + tc * 8 + 4];
            float4 xa = *(const float4*)&xsc[kk * XS_STRIDE + tr * 8];
            float4 xb = *(const float4*)&xsc[kk * XS_STRIDE + tr * 8 + 4];
            unsigned long long xd;
            PACK_DUP(xd, xa.x);
            FMA2(acc2[0][0], xd, w0.x); FMA2(acc2[0][1], xd, w0.y);
            FMA2(acc2[0][2], xd, w1.x); FMA2(acc2[0][3], xd, w1.y);
            PACK_DUP(xd, xa.y);
            FMA2(acc2[1][0], xd, w0.x); FMA2(acc2[1][1], xd, w0.y);
            FMA2(acc2[1][2], xd, w1.x); FMA2(acc2[1][3], xd, w1.y);
            PACK_DUP(xd, xa.z);
            FMA2(acc2[2][0], xd, w0.x); FMA2(acc2[2][1], xd, w0.y);
            FMA2(acc2[2][2], xd, w1.x); FMA2(acc2[2][3], xd, w1.y);
            PACK_DUP(xd, xa.w);
            FMA2(acc2[3][0], xd, w0.x); FMA2(acc2[3][1], xd, w0.y);
            FMA2(acc2[3][2], xd, w1.x); FMA2(acc2[3][3], xd, w1.y);
            PACK_DUP(xd, xb.x);
            FMA2(acc2[4][0], xd, w0.x); FMA2(acc2[4][1], xd, w0.y);
            FMA2(acc2[4][2], xd, w1.x); FMA2(acc2[4][3], xd, w1.y);
            PACK_DUP(xd, xb.y);
            FMA2(acc2[5][0], xd, w0.x); FMA2(acc2[5][1], xd, w0.y);
            FMA2(acc2[5][2], xd, w1.x); FMA2(acc2[5][3], xd, w1.y);
            PACK_DUP(xd, xb.z);
            FMA2(acc2[6][0], xd, w0.x); FMA2(acc2[6][1], xd, w0.y);
            FMA2(acc2[6][2], xd, w1.x); FMA2(acc2[6][3], xd, w1.y);
            PACK_DUP(xd, xb.w);
            FMA2(acc2[7][0], xd, w0.x); FMA2(acc2[7][1], xd, w0.y);
            FMA2(acc2[7][2], xd, w1.x); FMA2(acc2[7][3], xd, w1.y);
        }
    }

#pragma unroll
    for (int i = 0; i < 8; i++) {
        int row = rowbase + tr * 8 + i;
        if (row < N_NODES) {
            float f0, f1, f2, f3, f4, f5, f6, f7;
            UNPACK2(f0, f1, acc2[i][0]);
            UNPACK2(f2, f3, acc2[i][1]);
            UNPACK2(f4, f5, acc2[i][2]);
            UNPACK2(f6, f7, acc2[i][3]);
            float* h0p = g_h0 + (size_t)row * HID + tc * 8;
            *(float4*)&h0p[0] = make_float4(f0, f1, f2, f3);
            *(float4*)&h0p[4] = make_float4(f4, f5, f6, f7);
            __half2 p0 = __floats2half2_rn(f0, f1);
            __half2 p1 = __floats2half2_rn(f2, f3);
            __half2 p2 = __floats2half2_rn(f4, f5);
            __half2 p3 = __floats2half2_rn(f6, f7);
            uint4 ov;
            ov.x = *(unsigned*)&p0;
            ov.y = *(unsigned*)&p1;
            ov.z = *(unsigned*)&p2;
            ov.w = *(unsigned*)&p3;
            *(uint4*)(g_h16A + (size_t)row * HID2 + tc * 4) = ov;
        }
    }
}

// ---------------- APPNP propagation (R13/R11 form — best measured) ------------
// Warp-per-node, 4 edges per iteration: quarter-warps of 8 lanes, each lane
// loads one uint4 (16B) of the 128B fp16 row -> LDG.128, ~5 warp-instr/edge.
#define ACC8(n, v)                                              \
    do {                                                        \
        float2 _f0 = __half22float2(*(__half2*)&(v).x);         \
        float2 _f1 = __half22float2(*(__half2*)&(v).y);         \
        float2 _f2 = __half22float2(*(__half2*)&(v).z);         \
        float2 _f3 = __half22float2(*(__half2*)&(v).w);         \
        a0 = fmaf((n), _f0.x, a0);  a1 = fmaf((n), _f0.y, a1);  \
        a2 = fmaf((n), _f1.x, a2);  a3 = fmaf((n), _f1.y, a3);  \
        a4 = fmaf((n), _f2.x, a4);  a5 = fmaf((n), _f2.y, a5);  \
        a6 = fmaf((n), _f3.x, a6);  a7 = fmaf((n), _f3.y, a7);  \
    } while (0)

__global__ void __launch_bounds__(256) k_prop(int sin_sel, int sout_sel, int final_step) {
    const uint4* __restrict__ xin4 = (const uint4*)h16buf(sin_sel);   // row = 8 uint4
    uint4* __restrict__ xout4 = (uint4*)h16buf(sout_sel);

    const int node = (blockIdx.x * blockDim.x + threadIdx.x) >> 5;
    const int lane = threadIdx.x & 31;
    if (node >= N_NODES) return;

    const int beg = g_ptrF[node];
    const int end = g_ptrF[node + 1];
    const int deg = end - beg;
    const int nfull = deg & ~31;
    const int q   = lane >> 3;       // quarter id 0..3
    const int sub = lane & 7;        // uint4 index within 128B row

    float a0 = 0.f, a1 = 0.f, a2 = 0.f, a3 = 0.f;
    float a4 = 0.f, a5 = 0.f, a6 = 0.f, a7 = 0.f;

    int base = beg;
    for (; base < beg + nfull; base += 32) {
        int2 ed = g_edges[base + lane];
#pragma unroll
        for (int j = 0; j < 8; j++) {
            int   sl = j + q * 8;
            int   s  = __shfl_sync(0xffffffffu, ed.x, sl);
            float n  = __int_as_float(__shfl_sync(0xffffffffu, ed.y, sl));
            uint4 v  = xin4[(size_t)s * 8 + sub];
            ACC8(n, v);
        }
    }

    const int rem = deg - nfull;
    if (rem) {
        int idx = base + lane;
        int2 ed = (idx < end) ? g_edges[idx] : make_int2(0, 0);
        const int half = (rem + 3) >> 2;            // <= 8
        for (int j = 0; j < half; j++) {
            int   sl = j + q * half;                // <= 31
            int   s  = __shfl_sync(0xffffffffu, ed.x, sl);
            float n  = __int_as_float(__shfl_sync(0xffffffffu, ed.y, sl));
            uint4 v  = xin4[(size_t)s * 8 + sub];
            ACC8(n, v);
        }
    }

    a0 += __shfl_down_sync(0xffffffffu, a0, 16);
    a1 += __shfl_down_sync(0xffffffffu, a1, 16);
    a2 += __shfl_down_sync(0xffffffffu, a2, 16);
    a3 += __shfl_down_sync(0xffffffffu, a3, 16);
    a4 += __shfl_down_sync(0xffffffffu, a4, 16);
    a5 += __shfl_down_sync(0xffffffffu, a5, 16);
    a6 += __shfl_down_sync(0xffffffffu, a6, 16);
    a7 += __shfl_down_sync(0xffffffffu, a7, 16);
    a0 += __shfl_down_sync(0xffffffffu, a0, 8);
    a1 += __shfl_down_sync(0xffffffffu, a1, 8);
    a2 += __shfl_down_sync(0xffffffffu, a2, 8);
    a3 += __shfl_down_sync(0xffffffffu, a3, 8);
    a4 += __shfl_down_sync(0xffffffffu, a4, 8);
    a5 += __shfl_down_sync(0xffffffffu, a5, 8);
    a6 += __shfl_down_sync(0xffffffffu, a6, 8);
    a7 += __shfl_down_sync(0xffffffffu, a7, 8);

    if (lane < 8) {
        float dv = g_dinv[node];
        float sn = dv * dv;
        uint4 sv = xin4[(size_t)node * 8 + sub];
        {
            float2 f0 = __half22float2(*(__half2*)&sv.x);
            float2 f1 = __half22float2(*(__half2*)&sv.y);
            float2 f2 = __half22float2(*(__half2*)&sv.z);
            float2 f3 = __half22float2(*(__half2*)&sv.w);
            a0 = fmaf(sn, f0.x, a0);  a1 = fmaf(sn, f0.y, a1);
            a2 = fmaf(sn, f1.x, a2);  a3 = fmaf(sn, f1.y, a3);
            a4 = fmaf(sn, f2.x, a4);  a5 = fmaf(sn, f2.y, a5);
            a6 = fmaf(sn, f3.x, a6);  a7 = fmaf(sn, f3.y, a7);
        }

        const float4* h0p = (const float4*)(g_h0 + (size_t)node * HID) + sub * 2;
        float4 h0a = h0p[0];
        float4 h0b = h0p[1];
        float o0 = 0.9f * a0 + 0.1f * h0a.x;
        float o1 = 0.9f * a1 + 0.1f * h0a.y;
        float o2 = 0.9f * a2 + 0.1f * h0a.z;
        float o3 = 0.9f * a3 + 0.1f * h0a.w;
        float o4 = 0.9f * a4 + 0.1f * h0b.x;
        float o5 = 0.9f * a5 + 0.1f * h0b.y;
        float o6 = 0.9f * a6 + 0.1f * h0b.z;
        float o7 = 0.9f * a7 + 0.1f * h0b.w;

        __half2 p0 = __floats2half2_rn(o0, o1);
        __half2 p1 = __floats2half2_rn(o2, o3);
        __half2 p2 = __floats2half2_rn(o4, o5);
        __half2 p3 = __floats2half2_rn(o6, o7);
        uint4 ov;
        ov.x = *(unsigned*)&p0;
        ov.y = *(unsigned*)&p1;
        ov.z = *(unsigned*)&p2;
        ov.w = *(unsigned*)&p3;
        xout4[(size_t)node * 8 + sub] = ov;

        if (final_step) {
            float4* fo = (float4*)(g_hf32 + (size_t)node * HID) + sub * 2;
            fo[0] = make_float4(o0, o1, o2, o3);
            fo[1] = make_float4(o4, o5, o6, o7);
        }
    }
}

// ---------------- BN + lin2 + log_softmax (fused epilogue) --------------------
__global__ void __launch_bounds__(128) k_epilogue(const float* __restrict__ gamma,
                                                  const float* __restrict__ beta,
                                                  const float* __restrict__ mean,
                                                  const float* __restrict__ var,
                                                  const float* __restrict__ W2,
                                                  const float* __restrict__ b2,
                                                  float* __restrict__ out) {
    __shared__ float sc[HID], sh[HID];
    __shared__ float W2s[HID * OUT_DIM];
    __shared__ float b2s[OUT_DIM];

    const int tid = threadIdx.x;
    if (tid < HID) {
        float s = gamma[tid] * rsqrtf(var[tid] + 1e-5f);
        sc[tid] = s;
        sh[tid] = beta[tid] - mean[tid] * s;
    }
    if (tid < OUT_DIM) b2s[tid] = b2[tid];
    for (int i = tid; i < HID * OUT_DIM; i += 128) W2s[i] = W2[i];
    __syncthreads();

    int node = blockIdx.x * 128 + tid;
    if (node >= N_NODES) return;

    float acc[OUT_DIM];
#pragma unroll
    for (int j = 0; j < OUT_DIM; j++) acc[j] = b2s[j];

    const float* hp = g_hf32 + (size_t)node * HID;
    for (int k = 0; k < HID; k++) {
        float t = fmaf(hp[k], sc[k], sh[k]);
#pragma unroll
        for (int j = 0; j < OUT_DIM; j++)
            acc[j] = fmaf(t, W2s[k * OUT_DIM + j], acc[j]);
    }

    float m = acc[0];
#pragma unroll
    for (int j = 1; j < OUT_DIM; j++) m = fmaxf(m, acc[j]);
    float s = 0.f;
#pragma unroll
    for (int j = 0; j < OUT_DIM; j++) s += expf(acc[j] - m);
    float lse = m + logf(s);

    float* op = out + (size_t)node * OUT_DIM;
    float* ep = out + (size_t)N_NODES * OUT_DIM + (size_t)node * OUT_DIM;
#pragma unroll
    for (int j4 = 0; j4 < OUT_DIM / 4; j4++) {
        float4 e = make_float4(acc[4*j4], acc[4*j4+1], acc[4*j4+2], acc[4*j4+3]);
        float4 o = make_float4(e.x - lse, e.y - lse, e.z - lse, e.w - lse);
        *(float4*)&op[4 * j4] = o;
        *(float4*)&ep[4 * j4] = e;
    }
}

// ---------------- host launcher: fork gemm1 || edge-build, join before prop ----
extern "C" void kernel_launch(void* const* d_in, const int* in_sizes, int n_in,
                              void* d_out, int out_size) {
    const float* x     = (const float*)d_in[0];
    const int*   ei    = (const int*)d_in[1];     // int64 inputs delivered as int32
    const float* W1    = (const float*)d_in[2];
    const float* b1    = (const float*)d_in[3];
    const float* gamma = (const float*)d_in[4];
    const float* beta  = (const float*)d_in[5];
    const float* mean  = (const float*)d_in[6];
    const float* var   = (const float*)d_in[7];
    const float* W2    = (const float*)d_in[8];
    const float* b2    = (const float*)d_in[9];
    float*       out   = (float*)d_out;

    // host-side objects created once (no device memory involved)
    static cudaStream_t s2 = [] {
        cudaStream_t s; cudaStreamCreateWithFlags(&s, cudaStreamNonBlocking); return s;
    }();
    static cudaEvent_t evFork = [] {
        cudaEvent_t e; cudaEventCreateWithFlags(&e, cudaEventDisableTiming); return e;
    }();
    static cudaEvent_t evJoin = [] {
        cudaEvent_t e; cudaEventCreateWithFlags(&e, cudaEventDisableTiming); return e;
    }();

    // fork: gemm1 (independent of edge data) on side stream
    cudaEventRecord(evFork, 0);
    cudaStreamWaitEvent(s2, evFork, 0);
    k_gemm1<<<NB_G, 128, 0, s2>>>(x, W1, b1);
    cudaEventRecord(evJoin, s2);

    // edge-build chain on main stream (concurrent with gemm1)
    k_count<<<NB_E, 256>>>(ei + N_EDGES);
    k_scanA<<<NUM_TILES, SCAN_TILE>>>();
    k_scatter<<<NB_E, 256>>>(ei);

    // join: prop needs both g_h16A/g_h0 (gemm1) and g_edges/g_ptrF (build)
    cudaStreamWaitEvent(0, evJoin, 0);

    const int prop_blocks = (N_NODES * 32 + 255) / 256;
    for (int s = 0; s < K_STEPS; s++)
        k_prop<<<prop_blocks, 256>>>(s & 1, (s & 1) ^ 1, s == K_STEPS - 1);

    k_epilogue<<<(N_NODES + 127) / 128, 128>>>(gamma, beta, mean, var, W2, b2, out);
}